// round 2
// baseline (speedup 1.0000x reference)
#include <cuda_runtime.h>
#include <math.h>

#define DIM 1024
#define INNER 1024
#define SEQ 2048
#define BATCH 4
#define HEADS 16
#define HEAD_DIM 64
#define ROWS (BATCH*SEQ)            // 8192
#define ATTN_SMEM (4*64*68*4)       // q_s,k_s,v_s,p_s tiles, padded rows

// Scratch (no runtime allocation allowed)
__device__ float g_xn[(size_t)ROWS * DIM];
__device__ float g_qkv[(size_t)ROWS * 3 * INNER];
__device__ float g_attn[(size_t)ROWS * INNER];

// ---------------------------------------------------------------------------
// LayerNorm: one block per row of 1024, 256 threads, float4 per thread
// ---------------------------------------------------------------------------
__global__ void ln_kernel(const float* __restrict__ x, const float* __restrict__ g,
                          const float* __restrict__ beta, float* __restrict__ out) {
    int row = blockIdx.x;
    int t = threadIdx.x;
    const float4* xr = (const float4*)(x + (size_t)row * DIM);
    float4 v = xr[t];
    float s  = v.x + v.y + v.z + v.w;
    float ss = v.x*v.x + v.y*v.y + v.z*v.z + v.w*v.w;
    #pragma unroll
    for (int o = 16; o; o >>= 1) {
        s  += __shfl_xor_sync(0xffffffffu, s,  o);
        ss += __shfl_xor_sync(0xffffffffu, ss, o);
    }
    __shared__ float sbuf[8], ssbuf[8];
    __shared__ float mu_s, rstd_s;
    if ((t & 31) == 0) { sbuf[t >> 5] = s; ssbuf[t >> 5] = ss; }
    __syncthreads();
    if (t == 0) {
        float st = 0.f, sst = 0.f;
        #pragma unroll
        for (int i = 0; i < 8; i++) { st += sbuf[i]; sst += ssbuf[i]; }
        float mu  = st * (1.0f / DIM);
        float var = sst * (1.0f / DIM) - mu * mu;
        mu_s = mu;
        rstd_s = rsqrtf(var + 1e-5f);
    }
    __syncthreads();
    float mu = mu_s, rstd = rstd_s;
    float4 gv = ((const float4*)g)[t];
    float4 bv = ((const float4*)beta)[t];
    float4 o4;
    o4.x = (v.x - mu) * rstd * gv.x + bv.x;
    o4.y = (v.y - mu) * rstd * gv.y + bv.y;
    o4.z = (v.z - mu) * rstd * gv.z + bv.z;
    o4.w = (v.w - mu) * rstd * gv.w + bv.w;
    ((float4*)(out + (size_t)row * DIM))[t] = o4;
}

// ---------------------------------------------------------------------------
// GEMM + bias: C[M,N] = A[M,K] @ B[K,N] + bias[N]
// 64x64 block tile, BK=16, 256 threads, 4x4 per thread
// ---------------------------------------------------------------------------
__global__ void gemm_bias_kernel(const float* __restrict__ A, const float* __restrict__ B,
                                 const float* __restrict__ bias, float* __restrict__ C,
                                 int M, int N, int K) {
    __shared__ float As[16][64];   // As[k][m]
    __shared__ float Bs[16][64];   // Bs[k][n]
    int t  = threadIdx.x;
    int tm = t >> 4;               // 0..15
    int tn = t & 15;               // 0..15
    int m0 = blockIdx.y << 6;
    int n0 = blockIdx.x << 6;

    int arow = t >> 2;             // 0..63
    int ak   = (t & 3) << 2;       // 0,4,8,12
    int bk   = t >> 4;             // 0..15
    int bn   = (t & 15) << 2;      // 0..60

    const float* Ap = A + (size_t)(m0 + arow) * K + ak;
    const float* Bp = B + (size_t)bk * N + n0 + bn;

    float acc[4][4] = {};

    for (int k0 = 0; k0 < K; k0 += 16) {
        float4 a = *(const float4*)(Ap + k0);
        float4 b = *(const float4*)(Bp + (size_t)k0 * N);
        As[ak + 0][arow] = a.x;
        As[ak + 1][arow] = a.y;
        As[ak + 2][arow] = a.z;
        As[ak + 3][arow] = a.w;
        *(float4*)&Bs[bk][bn] = b;
        __syncthreads();
        #pragma unroll
        for (int kk = 0; kk < 16; kk++) {
            float4 av = *(const float4*)&As[kk][tm << 2];
            float4 bv = *(const float4*)&Bs[kk][tn << 2];
            acc[0][0] += av.x * bv.x; acc[0][1] += av.x * bv.y; acc[0][2] += av.x * bv.z; acc[0][3] += av.x * bv.w;
            acc[1][0] += av.y * bv.x; acc[1][1] += av.y * bv.y; acc[1][2] += av.y * bv.z; acc[1][3] += av.y * bv.w;
            acc[2][0] += av.z * bv.x; acc[2][1] += av.z * bv.y; acc[2][2] += av.z * bv.z; acc[2][3] += av.z * bv.w;
            acc[3][0] += av.w * bv.x; acc[3][1] += av.w * bv.y; acc[3][2] += av.w * bv.z; acc[3][3] += av.w * bv.w;
        }
        __syncthreads();
    }

    float4 bb = *(const float4*)&bias[n0 + (tn << 2)];
    #pragma unroll
    for (int i = 0; i < 4; i++) {
        float4 o;
        o.x = acc[i][0] + bb.x;
        o.y = acc[i][1] + bb.y;
        o.z = acc[i][2] + bb.z;
        o.w = acc[i][3] + bb.w;
        *(float4*)&C[(size_t)(m0 + (tm << 2) + i) * N + n0 + (tn << 2)] = o;
    }
}

// ---------------------------------------------------------------------------
// Flash attention: grid (b*h = 64, qtile = 32), 256 threads.
// 64-query tile, iterate 32 kv tiles of 64. Online softmax.
// Each thread owns a 4x4 micro-tile of S and of O.
// Writes directly into [b, s, h*64+d] layout (fuses the transpose).
// ---------------------------------------------------------------------------
__global__ void attn_kernel(const float* __restrict__ qkv, float* __restrict__ out) {
    extern __shared__ float sh[];
    float* q_s = sh;                 // [64][68]
    float* k_s = q_s + 64 * 68;
    float* v_s = k_s + 64 * 68;
    float* p_s = v_s + 64 * 68;

    int bh = blockIdx.x;
    int b  = bh >> 4;
    int h  = bh & 15;
    int qt = blockIdx.y;
    int t  = threadIdx.x;
    int tm = t >> 4;                 // 0..15 (row group)
    int tn = t & 15;                 // 0..15 (col group)
    const float scale = 0.125f;      // 1/sqrt(64)

    int lr = t >> 2;                 // 0..63 loader row
    int lc = (t & 3) << 4;           // 0,16,32,48 loader col

    // Load Q tile
    {
        size_t qbase = ((size_t)(b * SEQ + (qt << 6) + lr)) * (3 * INNER) + h * HEAD_DIM + lc;
        #pragma unroll
        for (int q4 = 0; q4 < 4; q4++)
            *(float4*)&q_s[lr * 68 + lc + (q4 << 2)] = *(const float4*)(qkv + qbase + (q4 << 2));
    }

    float o[4][4] = {};
    float m_i[4], l_i[4];
    #pragma unroll
    for (int i = 0; i < 4; i++) { m_i[i] = -1e30f; l_i[i] = 0.f; }

    for (int kt = 0; kt < SEQ / 64; kt++) {
        __syncthreads();   // previous O-update consumers of v_s/p_s done
        // Load K and V tiles
        size_t kbase = ((size_t)(b * SEQ + (kt << 6) + lr)) * (3 * INNER) + INNER + h * HEAD_DIM + lc;
        #pragma unroll
        for (int q4 = 0; q4 < 4; q4++) {
            *(float4*)&k_s[lr * 68 + lc + (q4 << 2)] = *(const float4*)(qkv + kbase + (q4 << 2));
            *(float4*)&v_s[lr * 68 + lc + (q4 << 2)] = *(const float4*)(qkv + kbase + INNER + (q4 << 2));
        }
        __syncthreads();

        // S = Q K^T (4x4 per thread)
        float s[4][4] = {};
        #pragma unroll
        for (int d = 0; d < HEAD_DIM; d += 4) {
            float4 qa[4], kb[4];
            #pragma unroll
            for (int i = 0; i < 4; i++) qa[i] = *(const float4*)&q_s[((tm << 2) + i) * 68 + d];
            #pragma unroll
            for (int j = 0; j < 4; j++) kb[j] = *(const float4*)&k_s[((tn << 2) + j) * 68 + d];
            #pragma unroll
            for (int i = 0; i < 4; i++)
                #pragma unroll
                for (int j = 0; j < 4; j++)
                    s[i][j] += qa[i].x * kb[j].x + qa[i].y * kb[j].y
                             + qa[i].z * kb[j].z + qa[i].w * kb[j].w;
        }

        // Online softmax per row (row stats shared across the 16 tn-threads,
        // which are 16 contiguous lanes of the same warp)
        #pragma unroll
        for (int i = 0; i < 4; i++) {
            float mt = -1e30f;
            #pragma unroll
            for (int j = 0; j < 4; j++) { s[i][j] *= scale; mt = fmaxf(mt, s[i][j]); }
            #pragma unroll
            for (int o2 = 8; o2; o2 >>= 1) mt = fmaxf(mt, __shfl_xor_sync(0xffffffffu, mt, o2));
            float m_new = fmaxf(m_i[i], mt);
            float corr = __expf(m_i[i] - m_new);
            float ls = 0.f;
            #pragma unroll
            for (int j = 0; j < 4; j++) { s[i][j] = __expf(s[i][j] - m_new); ls += s[i][j]; }
            #pragma unroll
            for (int o2 = 8; o2; o2 >>= 1) ls += __shfl_xor_sync(0xffffffffu, ls, o2);
            l_i[i] = l_i[i] * corr + ls;
            m_i[i] = m_new;
            #pragma unroll
            for (int j = 0; j < 4; j++) o[i][j] *= corr;
            *(float4*)&p_s[((tm << 2) + i) * 68 + (tn << 2)] =
                make_float4(s[i][0], s[i][1], s[i][2], s[i][3]);
        }
        __syncthreads();

        // O += P @ V  (4x4 per thread, full 64-deep k loop)
        #pragma unroll 4
        for (int k = 0; k < 64; k++) {
            float4 vv = *(const float4*)&v_s[k * 68 + (tn << 2)];
            float p0 = p_s[((tm << 2) + 0) * 68 + k];
            float p1 = p_s[((tm << 2) + 1) * 68 + k];
            float p2 = p_s[((tm << 2) + 2) * 68 + k];
            float p3 = p_s[((tm << 2) + 3) * 68 + k];
            o[0][0] += p0 * vv.x; o[0][1] += p0 * vv.y; o[0][2] += p0 * vv.z; o[0][3] += p0 * vv.w;
            o[1][0] += p1 * vv.x; o[1][1] += p1 * vv.y; o[1][2] += p1 * vv.z; o[1][3] += p1 * vv.w;
            o[2][0] += p2 * vv.x; o[2][1] += p2 * vv.y; o[2][2] += p2 * vv.z; o[2][3] += p2 * vv.w;
            o[3][0] += p3 * vv.x; o[3][1] += p3 * vv.y; o[3][2] += p3 * vv.z; o[3][3] += p3 * vv.w;
        }
    }

    // Finalize: divide by l, write to [b, s, h*64 + d] (fused transpose)
    #pragma unroll
    for (int i = 0; i < 4; i++) {
        float inv = 1.0f / l_i[i];
        size_t obase = ((size_t)(b * SEQ + (qt << 6) + (tm << 2) + i)) * INNER
                     + h * HEAD_DIM + (tn << 2);
        float4 ov = make_float4(o[i][0] * inv, o[i][1] * inv, o[i][2] * inv, o[i][3] * inv);
        *(float4*)(out + obase) = ov;
    }
}

// ---------------------------------------------------------------------------
extern "C" void kernel_launch(void* const* d_in, const int* in_sizes, int n_in,
                              void* d_out, int out_size) {
    const float* x     = (const float*)d_in[0];
    const float* ln_g  = (const float*)d_in[1];
    const float* ln_b  = (const float*)d_in[2];
    const float* w_qkv = (const float*)d_in[3];
    const float* b_qkv = (const float*)d_in[4];
    const float* w_out = (const float*)d_in[5];
    const float* b_out = (const float*)d_in[6];
    float* out = (float*)d_out;

    float *xn, *qkv, *attn;
    cudaGetSymbolAddress((void**)&xn,   g_xn);
    cudaGetSymbolAddress((void**)&qkv,  g_qkv);
    cudaGetSymbolAddress((void**)&attn, g_attn);

    cudaFuncSetAttribute(attn_kernel, cudaFuncAttributeMaxDynamicSharedMemorySize, ATTN_SMEM);

    // 1) LayerNorm
    ln_kernel<<<ROWS, 256>>>(x, ln_g, ln_b, xn);
    // 2) QKV projection: [8192,1024] @ [1024,3072] + bias
    gemm_bias_kernel<<<dim3((3 * INNER) / 64, ROWS / 64), 256>>>(xn, w_qkv, b_qkv, qkv,
                                                                 ROWS, 3 * INNER, DIM);
    // 3) Attention (writes [b,s,inner] directly)
    attn_kernel<<<dim3(BATCH * HEADS, SEQ / 64), 256, ATTN_SMEM>>>(qkv, attn);
    // 4) Output projection: [8192,1024] @ [1024,1024] + bias
    gemm_bias_kernel<<<dim3(DIM / 64, ROWS / 64), 256>>>(attn, w_out, b_out, out,
                                                         ROWS, DIM, INNER);
}